// round 17
// baseline (speedup 1.0000x reference)
#include <cuda_runtime.h>
#include <cuda_fp16.h>
#include <cstdint>

#define N_DIM 384
#define S_DIM 64
#define C_IN  64
#define C_H   32
#define C_OUT 128
#define LN_EPS 1e-5f
#define NTILE 2304          // 48 x 48
#define GRID_MAIN 148

// ---------------- device scratch ----------------
__device__ __half g_A[N_DIM * C_H * S_DIM];      // [n][c][s] fp16
__device__ __half g_B[N_DIM * C_H * S_DIM];      // [n][d][s] fp16
__device__ __half g_W[16 * C_OUT * 64];          // [cidx][o][kk] fp16
__device__ unsigned long long g_mbits[N_DIM];

#define SWZ(b) ((b) ^ (((b) >> 3) & 0x70))

__device__ __forceinline__ uint32_t smem_u32(const void* p) {
    uint32_t a;
    asm("{ .reg .u64 t; cvta.to.shared.u64 t, %1; cvt.u32.u64 %0, t; }" : "=r"(a) : "l"(p));
    return a;
}
__device__ __forceinline__ void ldsm4(uint32_t r[4], uint32_t a) {
    asm volatile("ldmatrix.sync.aligned.m8n8.x4.shared.b16 {%0,%1,%2,%3}, [%4];"
                 : "=r"(r[0]), "=r"(r[1]), "=r"(r[2]), "=r"(r[3]) : "r"(a));
}
__device__ __forceinline__ void mma16816(float c[4], const uint32_t a[4], const uint32_t b[2]) {
    asm volatile("mma.sync.aligned.m16n8k16.row.col.f32.f16.f16.f32 "
                 "{%0,%1,%2,%3}, {%4,%5,%6,%7}, {%8,%9}, {%0,%1,%2,%3};"
                 : "+f"(c[0]), "+f"(c[1]), "+f"(c[2]), "+f"(c[3])
                 : "r"(a[0]), "r"(a[1]), "r"(a[2]), "r"(a[3]), "r"(b[0]), "r"(b[1]));
}
#define CP16(dst, src) asm volatile("cp.async.cg.shared.global [%0], [%1], 16;" :: "r"(dst), "l"(src))
#define CP_COMMIT()    asm volatile("cp.async.commit_group;" ::: "memory")
#define CP_WAIT(n)     asm volatile("cp.async.wait_group %0;" :: "n"(n) : "memory")

// ---------------------------------------------------------------------------
// fused prep + wo kernel (unchanged).
// ---------------------------------------------------------------------------
__global__ __launch_bounds__(512, 3) void prep_kernel(
    const float* __restrict__ m, const int* __restrict__ mask,
    const float* __restrict__ gamma, const float* __restrict__ beta,
    const float* __restrict__ Wa, const float* __restrict__ Wb,
    const float* __restrict__ Wo)
{
    __shared__ float sWa[C_H * 68];
    __shared__ float sWb[C_H * 68];
    __shared__ float sMn[16][C_IN];
    __shared__ __half sa[C_H * 34];
    __shared__ __half sb[C_H * 34];

    int tid = threadIdx.x, w = tid >> 5, l = tid & 31;
    int b = blockIdx.x;

    if (b >= 2 * N_DIM) {
        __shared__ float rowv[1024];
        int o = b - 2 * N_DIM;
        for (int i = tid; i < 1024; i += 512) rowv[i] = Wo[o * 1024 + i];
        __syncthreads();
        for (int r = tid; r < 1024; r += 512) {
            int cidx = r >> 6, kk = r & 63;
            int sl = cidx >> 2, ksub = cidx & 3;
            int c = sl * 8 + ksub * 2 + (kk >> 5), d = kk & 31;
            g_W[cidx * 8192 + o * 64 + kk] = __float2half(rowv[c * 32 + d]);
        }
        return;
    }

    int n = b >> 1, sh = b & 1;

    for (int i = tid; i < C_H * C_IN; i += 512) {
        int c = i >> 6, k = i & 63;
        sWa[c * 68 + k] = Wa[i];
        sWb[c * 68 + k] = Wb[i];
    }
    __syncthreads();

    float gam0 = gamma[l], gam1 = gamma[l + 32];
    float bet0 = beta[l],  bet1 = beta[l + 32];
    const float* wa = &sWa[l * 68];
    const float* wb = &sWb[l * 68];

    #pragma unroll
    for (int it = 0; it < 2; it++) {
        int sloc = it * 16 + w;
        int s = sh * 32 + sloc;
        int row = s * N_DIM + n;
        const float* mp = m + (size_t)row * C_IN;
        float v0 = mp[l], v1 = mp[l + 32];
        float sum = v0 + v1;
        #pragma unroll
        for (int o = 16; o; o >>= 1) sum += __shfl_xor_sync(0xffffffffu, sum, o);
        float mu = sum * (1.f / 64.f);
        float d0 = v0 - mu, d1 = v1 - mu;
        float sq = d0 * d0 + d1 * d1;
        #pragma unroll
        for (int o = 16; o; o >>= 1) sq += __shfl_xor_sync(0xffffffffu, sq, o);
        float inv = rsqrtf(sq * (1.f / 64.f) + LN_EPS);
        sMn[w][l]      = d0 * inv * gam0 + bet0;
        sMn[w][l + 32] = d1 * inv * gam1 + bet1;
        __syncwarp();
        float mf = (float)mask[row];
        float aa = 0.f, bb = 0.f;
        #pragma unroll
        for (int k4 = 0; k4 < 16; k4++) {
            float4 x  = *(const float4*)&sMn[w][k4 * 4];
            float4 A4 = *(const float4*)&wa[k4 * 4];
            float4 B4 = *(const float4*)&wb[k4 * 4];
            aa += x.x * A4.x + x.y * A4.y + x.z * A4.z + x.w * A4.w;
            bb += x.x * B4.x + x.y * B4.y + x.z * B4.z + x.w * B4.w;
        }
        sa[l * 34 + sloc] = __float2half(aa * mf);
        sb[l * 34 + sloc] = __float2half(bb * mf);
        __syncwarp();
    }
    __syncthreads();

    for (int e = tid; e < C_H * 32; e += 512) {
        int c = e >> 5, sloc = e & 31;
        size_t go = (size_t)n * 2048 + (size_t)c * 64 + sh * 32 + sloc;
        g_A[go] = sa[c * 34 + sloc];
        g_B[go] = sb[c * 34 + sloc];
    }

    if (sh == 0 && w == 0) {
        unsigned b0 = __ballot_sync(0xffffffffu, mask[l * N_DIM + n] != 0);
        unsigned b1 = __ballot_sync(0xffffffffu, mask[(l + 32) * N_DIM + n] != 0);
        if (l == 0) g_mbits[n] = (unsigned long long)b0 | ((unsigned long long)b1 << 32);
    }
}

// ---------------------------------------------------------------------------
// persistent main: 148 CTAs loop over 2304 tiles (8i x 8j each).
// Per slice sl, Wo chunks cidx = sl*4+ks occupy the 4 Wo buffers (64 KB group).
// A/B double-buffered via cp.async (prefetch next tile at S_end(2)).
// smem: As0 32K | As1 32K | Bs0 32K | Bs1 32K | Zs 32K | Wo 4x16K | iv
// Group order/tile: [tile start: AB, Wo_s0 pending] Wo_s1, Wo_s2, Wo_s3,
//                   AB_next, Wo_s0_next.
// ---------------------------------------------------------------------------
#define OFF_AS0 0u
#define OFF_AS1 32768u
#define OFF_BS0 65536u
#define OFF_BS1 98304u
#define OFF_ZS  131072u
#define OFF_WO  163840u
#define OFF_IV  229376u
#define SMEM_BYTES (229376 + 256)

#define ZOFF(ks, rel) (OFF_ZS + (uint32_t)(ks) * 8192u + (SWZ((uint32_t)(rel)) ^ ((uint32_t)(ks) << 4)))

// commit one full Wo slice (4 chunks = 64 KB) as ONE cp.async group
__device__ __forceinline__ void commit_wo_slice(uint32_t smb, int tid, int slice) {
    #pragma unroll
    for (int ks = 0; ks < 4; ks++) {
        const char* srcW = (const char*)g_W + (size_t)(slice * 4 + ks) * 16384;
        uint32_t dst = smb + OFF_WO + (uint32_t)ks * 16384u;
        #pragma unroll
        for (int q = 0; q < 4; q++) {
            uint32_t rel = (uint32_t)(tid + q * 256) * 16u;
            CP16(dst + SWZ(rel), srcW + rel);
        }
    }
    CP_COMMIT();
}

__global__ void __launch_bounds__(256, 1) main_kernel(
    const float* __restrict__ bo, float* __restrict__ out)
{
    extern __shared__ char sm[];
    const uint32_t smb = smem_u32(sm);
    const int tid = threadIdx.x, wid = tid >> 5, lane = tid & 31;
    float* sInvd = (float*)(sm + OFF_IV);

    const int wm = wid >> 2, wn = wid & 3;
    const int lr = lane & 15;
    const int lc = (lane >> 4) << 4;
    const int mrow = lane >> 2;
    const int ncol = (lane & 3) * 2;
    const int pb = wm * 32, ob = wn * 32;
    const int mb = wm * 32, nb = wn * 64;

    float2 bo2[4];
    #pragma unroll
    for (int tn = 0; tn < 4; tn++)
        bo2[tn] = *(const float2*)(bo + ob + tn * 8 + ncol);

    // ---- prologue: AB(tile0) -> buf0 (group); Wo slice 0 (group) ----
    {
        int t0 = blockIdx.x;
        int i0 = (t0 / 48) * 8, j0 = (t0 % 48) * 8;
        const char* srcA = (const char*)g_A + (size_t)i0 * 4096;
        const char* srcB = (const char*)g_B + (size_t)j0 * 4096;
        #pragma unroll
        for (int q = 0; q < 8; q++) {
            uint32_t rel = (uint32_t)(tid + q * 256) * 16u;
            uint32_t sw = SWZ(rel);
            CP16(smb + OFF_AS0 + sw, srcA + rel);
            CP16(smb + OFF_BS0 + sw, srcB + rel);
        }
        CP_COMMIT();                      // AB group
        commit_wo_slice(smb, tid, 0);     // Wo slice-0 group
    }

    int cur = 0;
    for (int t = blockIdx.x; t < NTILE; t += GRID_MAIN) {
        const int i0 = (t / 48) * 8, j0 = (t % 48) * 8;
        const bool has_next = (t + GRID_MAIN < NTILE);

        __syncthreads();   // S0: prev epilogue done (sInvd safe to rewrite)

        if (tid < 64) {
            unsigned long long wv = g_mbits[i0 + (tid >> 3)] & g_mbits[j0 + (tid & 7)];
            sInvd[tid] = 1.f / fmaxf((float)__popcll(wv), 1.f);
        }
        CP_WAIT(1);        // AB(cur) landed (only Wo_s0 may remain)
        __syncthreads();   // S1: AB + sInvd visible

        const uint32_t asb = smb + (cur ? OFF_AS1 : OFF_AS0);
        const uint32_t bsb = smb + (cur ? OFF_BS1 : OFF_BS0);

        float acc2[2][4][4];
        #pragma unroll
        for (int a = 0; a < 2; a++)
            #pragma unroll
            for (int b = 0; b < 4; b++)
                #pragma unroll
                for (int c = 0; c < 4; c++) acc2[a][b][c] = 0.f;

        for (int sl = 0; sl < 4; sl++) {
            // ---- GEMM1 slice ----
            float acc1[2][8][4];
            #pragma unroll
            for (int a = 0; a < 2; a++)
                #pragma unroll
                for (int b = 0; b < 8; b++)
                    #pragma unroll
                    for (int c = 0; c < 4; c++) acc1[a][b][c] = 0.f;

            #pragma unroll
            for (int k = 0; k < 4; k++) {
                uint32_t af[2][4];
                #pragma unroll
                for (int tm = 0; tm < 2; tm++) {
                    int mm = mb + tm * 16 + lr;
                    int r = ((mm >> 3) << 5) + sl * 8 + (mm & 7);
                    ldsm4(af[tm], asb + SWZ((uint32_t)(r * 128 + k * 32 + lc)));
                }
                uint32_t bf[8][2];
                #pragma unroll
                for (int tp = 0; tp < 4; tp++) {
                    uint32_t q[4];
                    int nn = nb + tp * 16 + lr;
                    ldsm4(q, bsb + SWZ((uint32_t)(nn * 128 + k * 32 + lc)));
                    bf[2*tp][0] = q[0]; bf[2*tp+1][0] = q[1];
                    bf[2*tp][1] = q[2]; bf[2*tp+1][1] = q[3];
                }
                #pragma unroll
                for (int tm = 0; tm < 2; tm++)
                    #pragma unroll
                    for (int tn = 0; tn < 8; tn++)
                        mma16816(acc1[tm][tn], af[tm], bf[tn]);
            }

            // ---- remap Z -> Zs ----
            #pragma unroll
            for (int tm = 0; tm < 2; tm++) {
                #pragma unroll
                for (int tn = 0; tn < 8; tn++) {
                    int nn = nb + tn * 8 + ncol;
                    int j = nn >> 5, d = nn & 31;
                    #pragma unroll
                    for (int h = 0; h < 2; h++) {
                        int mm = mb + tm * 16 + mrow + h * 8;
                        int i = mm >> 3, cl = mm & 7;
                        uint32_t rel = (uint32_t)((i * 8 + j) * 128 + ((cl & 1) * 32 + d) * 2);
                        __half2 hv = __floats2half2_rn(acc1[tm][tn][h*2], acc1[tm][tn][h*2+1]);
                        *(__half2*)(sm + ZOFF(cl >> 1, rel)) = hv;
                    }
                }
            }

            // Wo slice sl must have landed.
            // sl<3 (or last tile): it's the only pending group -> wait(0).
            // sl==3 with next tile: AB_next still pending -> wait(1).
            if (sl < 3 || !has_next) { CP_WAIT(0); } else { CP_WAIT(1); }
            __syncthreads();   // S2: remap + Wo slice visible

            // ---- GEMM2: 16 steps (ks = t>>2 selects Zs AND Wo buffer) ----
            {
                uint32_t af[2][2][4];
                uint32_t bf[2][4][2];

                #pragma unroll
                for (int tm = 0; tm < 2; tm++) {
                    int p = pb + tm * 16 + lr;
                    ldsm4(af[0][tm], smb + ZOFF(0, p * 128 + lc));
                }
                #pragma unroll
                for (int tp = 0; tp < 2; tp++) {
                    uint32_t q[4];
                    int o = ob + tp * 16 + lr;
                    ldsm4(q, smb + OFF_WO + SWZ((uint32_t)(o * 128 + lc)));
                    bf[0][2*tp][0] = q[0]; bf[0][2*tp+1][0] = q[1];
                    bf[0][2*tp][1] = q[2]; bf[0][2*tp+1][1] = q[3];
                }

                #pragma unroll
                for (int st = 0; st < 16; st++) {
                    const int cb = st & 1, nx = cb ^ 1;
                    if (st < 15) {
                        const int tt = st + 1;
                        const int ks = tt >> 2, k = tt & 3;
                        #pragma unroll
                        for (int tm = 0; tm < 2; tm++) {
                            int p = pb + tm * 16 + lr;
                            ldsm4(af[nx][tm], smb + ZOFF(ks, p * 128 + k * 32 + lc));
                        }
                        uint32_t wbase = smb + OFF_WO + (uint32_t)ks * 16384u;
                        #pragma unroll
                        for (int tp = 0; tp < 2; tp++) {
                            uint32_t q[4];
                            int o = ob + tp * 16 + lr;
                            ldsm4(q, wbase + SWZ((uint32_t)(o * 128 + k * 32 + lc)));
                            bf[nx][2*tp][0] = q[0]; bf[nx][2*tp+1][0] = q[1];
                            bf[nx][2*tp][1] = q[2]; bf[nx][2*tp+1][1] = q[3];
                        }
                    }
                    #pragma unroll
                    for (int tm = 0; tm < 2; tm++)
                        #pragma unroll
                        for (int tn = 0; tn < 4; tn++)
                            mma16816(acc2[tm][tn], af[cb][tm], bf[cb][tn]);
                }
            }

            __syncthreads();   // S_end(sl): all warps done reading Zs + Wo bufs

            if (sl < 3) {
                commit_wo_slice(smb, tid, sl + 1);
                if (sl == 2 && has_next) {
                    int tn2 = t + GRID_MAIN;
                    int ni0 = (tn2 / 48) * 8, nj0 = (tn2 % 48) * 8;
                    const char* srcA = (const char*)g_A + (size_t)ni0 * 4096;
                    const char* srcB = (const char*)g_B + (size_t)nj0 * 4096;
                    uint32_t asn = smb + (cur ? OFF_AS0 : OFF_AS1);
                    uint32_t bsn = smb + (cur ? OFF_BS0 : OFF_BS1);
                    #pragma unroll
                    for (int q = 0; q < 8; q++) {
                        uint32_t rel = (uint32_t)(tid + q * 256) * 16u;
                        uint32_t sw = SWZ(rel);
                        CP16(asn + sw, srcA + rel);
                        CP16(bsn + sw, srcB + rel);
                    }
                    CP_COMMIT();
                }
            } else if (has_next) {
                commit_wo_slice(smb, tid, 0);   // slice 0 for next tile
            }
        }

        // ---- epilogue ----
        #pragma unroll
        for (int tm = 0; tm < 2; tm++) {
            #pragma unroll
            for (int h = 0; h < 2; h++) {
                int pair = pb + tm * 16 + mrow + h * 8;
                int i = pair >> 3, j = pair & 7;
                float invd = sInvd[pair];
                float* op = out + ((size_t)(i0 + i) * N_DIM + (j0 + j)) * C_OUT;
                #pragma unroll
                for (int tn = 0; tn < 4; tn++) {
                    float2 v;
                    v.x = acc2[tm][tn][h*2]   * invd + bo2[tn].x;
                    v.y = acc2[tm][tn][h*2+1] * invd + bo2[tn].y;
                    *(float2*)(op + ob + tn * 8 + ncol) = v;
                }
            }
        }

        cur ^= 1;
    }
}

// ---------------------------------------------------------------------------
extern "C" void kernel_launch(void* const* d_in, const int* in_sizes, int n_in,
                              void* d_out, int out_size)
{
    const float* m     = (const float*)d_in[0];
    const int*   mask  = (const int*)  d_in[1];
    const float* gamma = (const float*)d_in[2];
    const float* beta  = (const float*)d_in[3];
    const float* Wa    = (const float*)d_in[4];
    const float* Wb    = (const float*)d_in[5];
    const float* Wo    = (const float*)d_in[6];
    const float* bo    = (const float*)d_in[7];
    float* out = (float*)d_out;

    cudaFuncSetAttribute(main_kernel, cudaFuncAttributeMaxDynamicSharedMemorySize, SMEM_BYTES);

    prep_kernel<<<2 * N_DIM + C_OUT, 512>>>(m, mask, gamma, beta, Wa, Wb, Wo);

    main_kernel<<<GRID_MAIN, 256, SMEM_BYTES>>>(bo, out);
}